// round 1
// baseline (speedup 1.0000x reference)
#include <cuda_runtime.h>
#include <math.h>

#define BATCH   2
#define SEQ     2048
#define DMODEL  1024
#define NHEAD   16
#define DK      64
#define BHTOT   (BATCH*NHEAD)     // 32
#define NEGBIG  -1e8f

// ---------------- scratch (static device globals; no allocation) -------------
__device__ float g_Q[BHTOT*SEQ*DK];   // [b,h,s,dk]
__device__ float g_K[BHTOT*SEQ*DK];
__device__ float g_V[BHTOT*SEQ*DK];
__device__ float g_bias[BATCH*SEQ];   // 0 or -1e8 per key position
__device__ int   g_maskmode;          // 1 = byte mask, 0 = int32 mask

// ---------------- mask dtype detection + bias build ---------------------------
__global__ void detect_mask_kernel(const unsigned int* __restrict__ m) {
    __shared__ int flag;
    if (threadIdx.x == 0) flag = 0;
    __syncthreads();
    // If mask is int32 (values 0/1), every word's bytes 1..3 are zero.
    // If mask is 1-byte bool, 4096 random 0/1 bytes -> some high byte nonzero.
    for (int i = threadIdx.x; i < 1024; i += blockDim.x) {
        if (m[i] & 0xFFFFFF00u) flag = 1;
    }
    __syncthreads();
    if (threadIdx.x == 0) g_maskmode = flag;
}

__global__ void build_bias_kernel(const void* __restrict__ mask) {
    int i = blockIdx.x * blockDim.x + threadIdx.x;
    if (i >= BATCH * SEQ) return;
    bool masked;
    if (g_maskmode) masked = ((const unsigned char*)mask)[i] != 0;
    else            masked = ((const int*)mask)[i] != 0;
    g_bias[i] = masked ? NEGBIG : 0.0f;
}

// ---------------- QKV projection: out = X @ W^T + b, split to heads -----------
// X: [4096,1024], W: [1024,1024] (row n holds weights for output feature n).
// out stored as [b,h,s,dk].
__global__ __launch_bounds__(256) void qkv_gemm_kernel(
    const float* __restrict__ X, const float* __restrict__ W,
    const float* __restrict__ bias, float* __restrict__ out)
{
    __shared__ float As[8][128];
    __shared__ float Ws[8][128];
    const int tid  = threadIdx.x;
    const int m0   = blockIdx.y * 128;
    const int n0   = blockIdx.x * 128;
    const int row  = tid >> 1;          // 0..127
    const int koff = (tid & 1) * 4;     // 0 or 4
    const int tx   = tid & 15;
    const int ty   = tid >> 4;

    float acc[8][8];
    #pragma unroll
    for (int i = 0; i < 8; i++)
        #pragma unroll
        for (int j = 0; j < 8; j++) acc[i][j] = 0.0f;

    const float* Xp = X + (size_t)(m0 + row) * DMODEL + koff;
    const float* Wp = W + (size_t)(n0 + row) * DMODEL + koff;

    for (int k0 = 0; k0 < DMODEL; k0 += 8) {
        float4 a = *(const float4*)(Xp + k0);
        float4 w = *(const float4*)(Wp + k0);
        __syncthreads();
        As[koff+0][row] = a.x; As[koff+1][row] = a.y;
        As[koff+2][row] = a.z; As[koff+3][row] = a.w;
        Ws[koff+0][row] = w.x; Ws[koff+1][row] = w.y;
        Ws[koff+2][row] = w.z; Ws[koff+3][row] = w.w;
        __syncthreads();
        #pragma unroll
        for (int kk = 0; kk < 8; kk++) {
            float av[8], wv[8];
            *(float4*)&av[0] = *(const float4*)&As[kk][ty*8];
            *(float4*)&av[4] = *(const float4*)&As[kk][ty*8+4];
            *(float4*)&wv[0] = *(const float4*)&Ws[kk][tx*8];
            *(float4*)&wv[4] = *(const float4*)&Ws[kk][tx*8+4];
            #pragma unroll
            for (int i = 0; i < 8; i++)
                #pragma unroll
                for (int j = 0; j < 8; j++)
                    acc[i][j] += av[i] * wv[j];
        }
    }

    #pragma unroll
    for (int i = 0; i < 8; i++) {
        int m  = m0 + ty*8 + i;
        int bb = m >> 11;             // /SEQ
        int s  = m & (SEQ - 1);
        #pragma unroll
        for (int j = 0; j < 8; j++) {
            int n = n0 + tx*8 + j;
            int h = n >> 6;           // /DK
            int d = n & (DK - 1);
            out[((size_t)(bb*NHEAD + h)*SEQ + s)*DK + d] = acc[i][j] + bias[n];
        }
    }
}

// ---------------- fused flash attention (fp32, online softmax) ----------------
// CTA: 128 threads, 64 query rows. Loops over 32 key tiles of 64.
// smem: Qs[d][r] (transposed), KP[d][c] (K transposed, later reused as P[r][k]),
//       Vs[k][d], bs[64].
#define PAD 65

__global__ __launch_bounds__(128) void attn_kernel(float* __restrict__ out) {
    extern __shared__ float sm[];
    float (*Qs)[PAD] = reinterpret_cast<float(*)[PAD]>(sm);
    float (*KP)[PAD] = reinterpret_cast<float(*)[PAD]>(sm + 64*PAD);
    float (*Vs)[PAD] = reinterpret_cast<float(*)[PAD]>(sm + 2*64*PAD);
    float* bs        = sm + 3*64*PAD;

    const int tid  = threadIdx.x;
    const int w    = tid >> 5;
    const int lane = tid & 31;
    const int rg   = lane >> 3;       // 0..3
    const int cg   = lane & 7;        // 0..7
    const int r0   = w*16 + rg*4;     // this thread's 4 query rows (local)
    const int c0   = cg*8;            // this thread's 8 key cols  (local)

    const int bh = blockIdx.y;        // 0..31
    const int q0 = blockIdx.x * 64;
    const float* Qb = g_Q + ((size_t)bh*SEQ + q0) * DK;
    const float* Kb = g_K + (size_t)bh*SEQ*DK;
    const float* Vb = g_V + (size_t)bh*SEQ*DK;
    const int bias_base = (bh >> 4) * SEQ;   // b*SEQ

    // load Q tile (64x64), transposed into Qs[d][r]
    #pragma unroll
    for (int it = 0; it < 8; it++) {
        int idx = it*512 + tid*4;
        int r = idx >> 6, d = idx & 63;
        float4 v = *(const float4*)&Qb[r*DK + d];
        Qs[d+0][r] = v.x; Qs[d+1][r] = v.y; Qs[d+2][r] = v.z; Qs[d+3][r] = v.w;
    }

    float m[4], l[4], o[4][8];
    #pragma unroll
    for (int i = 0; i < 4; i++) {
        m[i] = -INFINITY; l[i] = 0.0f;
        #pragma unroll
        for (int j = 0; j < 8; j++) o[i][j] = 0.0f;
    }

    for (int t = 0; t < SEQ/64; t++) {
        __syncthreads();   // previous PV reads done before overwriting K/V
        // load K tile transposed into KP[d][c], V tile natural into Vs[k][d]
        #pragma unroll
        for (int it = 0; it < 8; it++) {
            int idx = it*512 + tid*4;
            int c = idx >> 6, d = idx & 63;
            float4 kv = *(const float4*)&Kb[(size_t)(t*64 + c)*DK + d];
            KP[d+0][c] = kv.x; KP[d+1][c] = kv.y; KP[d+2][c] = kv.z; KP[d+3][c] = kv.w;
            float4 vv = *(const float4*)&Vb[(size_t)(t*64 + c)*DK + d];
            Vs[c][d+0] = vv.x; Vs[c][d+1] = vv.y; Vs[c][d+2] = vv.z; Vs[c][d+3] = vv.w;
        }
        if (tid < 64) bs[tid] = g_bias[bias_base + t*64 + tid];
        __syncthreads();

        // S = Q K^T (per-thread 4x8 tile)
        float s[4][8];
        #pragma unroll
        for (int i = 0; i < 4; i++)
            #pragma unroll
            for (int j = 0; j < 8; j++) s[i][j] = 0.0f;
        #pragma unroll 8
        for (int d = 0; d < DK; d++) {
            float qa[4], kb[8];
            #pragma unroll
            for (int i = 0; i < 4; i++) qa[i] = Qs[d][r0+i];
            #pragma unroll
            for (int j = 0; j < 8; j++) kb[j] = KP[d][c0+j];
            #pragma unroll
            for (int i = 0; i < 4; i++)
                #pragma unroll
                for (int j = 0; j < 8; j++) s[i][j] += qa[i]*kb[j];
        }

        // scale + mask bias, online softmax stats (reduce over cg via shfl)
        const float inv = 0.125f;   // 1/sqrt(64)
        float tm[4];
        #pragma unroll
        for (int i = 0; i < 4; i++) {
            tm[i] = -INFINITY;
            #pragma unroll
            for (int j = 0; j < 8; j++) {
                s[i][j] = s[i][j]*inv + bs[c0+j];
                tm[i] = fmaxf(tm[i], s[i][j]);
            }
            #pragma unroll
            for (int off = 1; off < 8; off <<= 1)
                tm[i] = fmaxf(tm[i], __shfl_xor_sync(0xffffffffu, tm[i], off));
        }
        float alpha[4], tl[4];
        #pragma unroll
        for (int i = 0; i < 4; i++) {
            float mn = fmaxf(m[i], tm[i]);
            alpha[i] = __expf(m[i] - mn);
            m[i] = mn;
            tl[i] = 0.0f;
            #pragma unroll
            for (int j = 0; j < 8; j++) {
                float p = __expf(s[i][j] - mn);
                s[i][j] = p;
                tl[i] += p;
            }
            #pragma unroll
            for (int off = 1; off < 8; off <<= 1)
                tl[i] += __shfl_xor_sync(0xffffffffu, tl[i], off);
            l[i] = l[i]*alpha[i] + tl[i];
            #pragma unroll
            for (int j = 0; j < 8; j++) o[i][j] *= alpha[i];
        }

        __syncthreads();   // all threads done reading K before P overwrite
        #pragma unroll
        for (int i = 0; i < 4; i++)
            #pragma unroll
            for (int j = 0; j < 8; j++)
                KP[r0+i][c0+j] = s[i][j];   // reuse KP as P[r][k]
        __syncthreads();

        // O += P @ V  (per-thread 4 rows x 8 d-cols)
        #pragma unroll 8
        for (int k = 0; k < 64; k++) {
            float pv[4], vv[8];
            #pragma unroll
            for (int i = 0; i < 4; i++) pv[i] = KP[r0+i][k];
            #pragma unroll
            for (int j = 0; j < 8; j++) vv[j] = Vs[k][c0+j];
            #pragma unroll
            for (int i = 0; i < 4; i++)
                #pragma unroll
                for (int j = 0; j < 8; j++) o[i][j] += pv[i]*vv[j];
        }
    }

    // epilogue: out[b, q, h*DK + d]
    const int b = bh >> 4, h = bh & (NHEAD - 1);
    #pragma unroll
    for (int i = 0; i < 4; i++) {
        float invl = 1.0f / l[i];
        size_t base = ((size_t)b*SEQ + q0 + r0 + i)*DMODEL + h*DK + c0;
        #pragma unroll
        for (int j = 0; j < 8; j++)
            out[base + j] = o[i][j] * invl;
    }
}

// ---------------- launch -----------------------------------------------------
extern "C" void kernel_launch(void* const* d_in, const int* in_sizes, int n_in,
                              void* d_out, int out_size)
{
    const float* input = (const float*)d_in[0];
    const void*  mask  = d_in[1];
    const float* Wq    = (const float*)d_in[2];
    const float* bq    = (const float*)d_in[3];
    const float* Wk    = (const float*)d_in[4];
    const float* bk    = (const float*)d_in[5];
    const float* Wv    = (const float*)d_in[6];
    const float* bv    = (const float*)d_in[7];
    float* out = (float*)d_out;

    float *qp, *kp, *vp;
    cudaGetSymbolAddress((void**)&qp, g_Q);
    cudaGetSymbolAddress((void**)&kp, g_K);
    cudaGetSymbolAddress((void**)&vp, g_V);

    detect_mask_kernel<<<1, 256>>>((const unsigned int*)mask);
    build_bias_kernel<<<(BATCH*SEQ + 255)/256, 256>>>(mask);

    dim3 ggrid(DMODEL/128, (BATCH*SEQ)/128);   // (8, 32)
    qkv_gemm_kernel<<<ggrid, 256>>>(input, Wq, bq, qp);
    qkv_gemm_kernel<<<ggrid, 256>>>(input, Wk, bk, kp);
    qkv_gemm_kernel<<<ggrid, 256>>>(input, Wv, bv, vp);

    static int attn_smem_set = 0;
    const int smem_bytes = (3*64*PAD + 64) * sizeof(float);
    if (!attn_smem_set) {
        cudaFuncSetAttribute(attn_kernel,
                             cudaFuncAttributeMaxDynamicSharedMemorySize,
                             smem_bytes);
        attn_smem_set = 1;
    }
    dim3 agrid(SEQ/64, BHTOT);                 // (32, 32)
    attn_kernel<<<agrid, 128, smem_bytes>>>(out);
}

// round 2
// speedup vs baseline: 3.5025x; 3.5025x over previous
#include <cuda_runtime.h>
#include <math.h>

#define BATCH   2
#define SEQ     2048
#define DMODEL  1024
#define NHEAD   16
#define DK      64
#define BHTOT   (BATCH*NHEAD)     // 32
#define NEGBIG  -1e8f

// ---------------- scratch (static device globals; no allocation) -------------
__device__ float g_Q[BHTOT*SEQ*DK];   // [b,h,s,dk]
__device__ float g_K[BHTOT*SEQ*DK];
__device__ float g_V[BHTOT*SEQ*DK];
__device__ float g_bias[BATCH*SEQ];   // 0 or -1e8 per key position
__device__ int   g_maskmode;          // 1 = byte mask, 0 = int32 mask

// ---------------- helpers ----------------------------------------------------
__device__ __forceinline__ unsigned f2tf(float f) {
    unsigned u;
    asm("cvt.rna.tf32.f32 %0, %1;" : "=r"(u) : "f"(f));
    return u;
}

__device__ __forceinline__ void mma_tf32(float c[4],
    unsigned a0, unsigned a1, unsigned a2, unsigned a3,
    unsigned b0, unsigned b1)
{
    asm volatile(
        "mma.sync.aligned.m16n8k8.row.col.f32.tf32.tf32.f32 "
        "{%0,%1,%2,%3}, {%4,%5,%6,%7}, {%8,%9}, {%0,%1,%2,%3};"
        : "+f"(c[0]), "+f"(c[1]), "+f"(c[2]), "+f"(c[3])
        : "r"(a0), "r"(a1), "r"(a2), "r"(a3), "r"(b0), "r"(b1));
}

// ---------------- mask dtype detection + bias build ---------------------------
__global__ void detect_mask_kernel(const unsigned int* __restrict__ m) {
    __shared__ int flag;
    if (threadIdx.x == 0) flag = 0;
    __syncthreads();
    for (int i = threadIdx.x; i < 1024; i += blockDim.x) {
        if (m[i] & 0xFFFFFF00u) flag = 1;
    }
    __syncthreads();
    if (threadIdx.x == 0) g_maskmode = flag;
}

__global__ void build_bias_kernel(const void* __restrict__ mask) {
    int i = blockIdx.x * blockDim.x + threadIdx.x;
    if (i >= BATCH * SEQ) return;
    bool masked;
    if (g_maskmode) masked = ((const unsigned char*)mask)[i] != 0;
    else            masked = ((const int*)mask)[i] != 0;
    g_bias[i] = masked ? NEGBIG : 0.0f;
}

// ---------------- QKV projection (tf32 tensor cores) --------------------------
// out = X @ W^T + b, scattered to [b,h,s,dk].
// Tile 128x128x32, 8 warps, warp tile 32x64. Both X and W are K-contiguous:
// natural [row][k] smem layout works for A and B fragments of .row.col mma.
__global__ __launch_bounds__(256) void qkv_gemm_tc(
    const float* __restrict__ X, const float* __restrict__ W,
    const float* __restrict__ bias, float* __restrict__ out)
{
    __shared__ unsigned As[128][36];   // pad 36: frag LDS conflict-free, 144B rows (16B aligned)
    __shared__ unsigned Ws[128][36];

    const int tid  = threadIdx.x;
    const int warp = tid >> 5, lane = tid & 31;
    const int lr   = lane >> 2, qq = lane & 3;
    const int wr   = warp >> 1;          // 0..3 -> m offset wr*32
    const int wc   = warp & 1;           // 0..1 -> n offset wc*64
    const int m0   = blockIdx.y * 128;
    const int n0   = blockIdx.x * 128;

    const int trow = tid >> 3;           // 0..31
    const int tkq  = tid & 7;            // 0..7

    float acc[2][8][4];
    #pragma unroll
    for (int mt = 0; mt < 2; mt++)
        #pragma unroll
        for (int nt = 0; nt < 8; nt++)
            #pragma unroll
            for (int e = 0; e < 4; e++) acc[mt][nt][e] = 0.0f;

    float4 ra[4], rw[4];
    #pragma unroll
    for (int i = 0; i < 4; i++) {
        ra[i] = *(const float4*)&X[(size_t)(m0 + trow + 32*i) * DMODEL + tkq*4];
        rw[i] = *(const float4*)&W[(size_t)(n0 + trow + 32*i) * DMODEL + tkq*4];
    }

    for (int k0 = 0; k0 < DMODEL; k0 += 32) {
        __syncthreads();
        #pragma unroll
        for (int i = 0; i < 4; i++) {
            uint4 ua = make_uint4(f2tf(ra[i].x), f2tf(ra[i].y), f2tf(ra[i].z), f2tf(ra[i].w));
            *(uint4*)&As[trow + 32*i][tkq*4] = ua;
            uint4 uw = make_uint4(f2tf(rw[i].x), f2tf(rw[i].y), f2tf(rw[i].z), f2tf(rw[i].w));
            *(uint4*)&Ws[trow + 32*i][tkq*4] = uw;
        }
        __syncthreads();
        if (k0 + 32 < DMODEL) {
            #pragma unroll
            for (int i = 0; i < 4; i++) {
                ra[i] = *(const float4*)&X[(size_t)(m0 + trow + 32*i)*DMODEL + k0 + 32 + tkq*4];
                rw[i] = *(const float4*)&W[(size_t)(n0 + trow + 32*i)*DMODEL + k0 + 32 + tkq*4];
            }
        }
        #pragma unroll
        for (int ks = 0; ks < 4; ks++) {
            const int kb = ks * 8;
            unsigned a[2][4];
            #pragma unroll
            for (int mt = 0; mt < 2; mt++) {
                int r = wr*32 + mt*16 + lr;
                a[mt][0] = As[r    ][kb + qq];
                a[mt][1] = As[r + 8][kb + qq];
                a[mt][2] = As[r    ][kb + qq + 4];
                a[mt][3] = As[r + 8][kb + qq + 4];
            }
            #pragma unroll
            for (int nt = 0; nt < 8; nt++) {
                int c = wc*64 + nt*8 + lr;
                unsigned b0 = Ws[c][kb + qq];
                unsigned b1 = Ws[c][kb + qq + 4];
                mma_tf32(acc[0][nt], a[0][0], a[0][1], a[0][2], a[0][3], b0, b1);
                mma_tf32(acc[1][nt], a[1][0], a[1][1], a[1][2], a[1][3], b0, b1);
            }
        }
    }

    // epilogue: scatter to [b,h,s,dk] with bias
    #pragma unroll
    for (int mt = 0; mt < 2; mt++) {
        #pragma unroll
        for (int er = 0; er < 2; er++) {
            int m  = m0 + wr*32 + mt*16 + lr + er*8;
            int bb = m >> 11;
            int s  = m & (SEQ - 1);
            #pragma unroll
            for (int nt = 0; nt < 8; nt++) {
                int n = n0 + wc*64 + nt*8 + 2*qq;
                int h = n >> 6;
                int d = n & (DK - 1);
                float2 v;
                v.x = acc[mt][nt][er*2 + 0] + bias[n];
                v.y = acc[mt][nt][er*2 + 1] + bias[n + 1];
                *(float2*)&out[((size_t)(bb*NHEAD + h)*SEQ + s)*DK + d] = v;
            }
        }
    }
}

// ---------------- fused flash attention (tf32 tensor cores) -------------------
// CTA: 256 threads (8 warps), 128 query rows (16 per warp). 64-key tiles.
// S and O live in mma accumulators; P round-trips through per-warp smem.
#define QT   128
#define PQS  68    // Qs/Ps pad: frag bank = 4*(lane>>2)+lane%4 unique; 272B rows
#define PKS  68    // Ks pad (same fragment pattern as Q)
#define PVS  72    // Vs pad: frag bank = 8*(lane%4)+(lane>>2) unique; 288B rows

__global__ __launch_bounds__(256) void attn_tc_kernel(float* __restrict__ out) {
    extern __shared__ unsigned sm[];
    unsigned* Qs = sm;                        // QT * PQS   = 8704
    unsigned* Ks = Qs + QT*PQS;               // 64 * PKS   = 4352
    unsigned* Vs = Ks + 64*PKS;               // 64 * PVS   = 4608
    unsigned* Ps = Vs + 64*PVS;               // QT * PQS   = 8704
    float*    bs = (float*)(Ps + QT*PQS);     // 64

    const int tid  = threadIdx.x;
    const int warp = tid >> 5, lane = tid & 31;
    const int lr   = lane >> 2, qq = lane & 3;
    const int wrow = warp * 16;               // this warp's 16 q rows (local)

    const int bh = blockIdx.y;                // 0..31
    const int q0 = blockIdx.x * QT;
    const float* Qb = g_Q + ((size_t)bh*SEQ + q0) * DK;
    const float* Kb = g_K + (size_t)bh*SEQ*DK;
    const float* Vb = g_V + (size_t)bh*SEQ*DK;
    const int bias_base = (bh >> 4) * SEQ;    // b*SEQ

    // load Q tile (128x64) as tf32, natural [r][d] layout
    #pragma unroll
    for (int i = 0; i < 8; i++) {
        int t = tid + i*256;                  // 2048 float4 tasks
        int r = t >> 4, dq = t & 15;
        float4 v = *(const float4*)&Qb[(size_t)r*DK + 4*dq];
        uint4 u = make_uint4(f2tf(v.x), f2tf(v.y), f2tf(v.z), f2tf(v.w));
        *(uint4*)&Qs[r*PQS + 4*dq] = u;
    }

    float S[8][4], O[8][4];
    float mrow[2] = {-INFINITY, -INFINITY};
    float lrow[2] = {0.0f, 0.0f};
    #pragma unroll
    for (int nt = 0; nt < 8; nt++)
        #pragma unroll
        for (int e = 0; e < 4; e++) O[nt][e] = 0.0f;

    for (int t = 0; t < SEQ/64; t++) {
        __syncthreads();   // prior-iteration mma reads done before K/V overwrite
        #pragma unroll
        for (int i = 0; i < 4; i++) {
            int tk = tid + i*256;             // 1024 float4 tasks each for K,V
            int c = tk >> 4, dq = tk & 15;
            float4 kv = *(const float4*)&Kb[(size_t)(t*64 + c)*DK + 4*dq];
            *(uint4*)&Ks[c*PKS + 4*dq] =
                make_uint4(f2tf(kv.x), f2tf(kv.y), f2tf(kv.z), f2tf(kv.w));
            float4 vv = *(const float4*)&Vb[(size_t)(t*64 + c)*DK + 4*dq];
            *(uint4*)&Vs[c*PVS + 4*dq] =
                make_uint4(f2tf(vv.x), f2tf(vv.y), f2tf(vv.z), f2tf(vv.w));
        }
        if (tid < 64) bs[tid] = g_bias[bias_base + t*64 + tid];
        __syncthreads();

        // ---- S = Q K^T ----
        #pragma unroll
        for (int nt = 0; nt < 8; nt++)
            #pragma unroll
            for (int e = 0; e < 4; e++) S[nt][e] = 0.0f;
        #pragma unroll
        for (int ks = 0; ks < 8; ks++) {
            const int kb = ks * 8;
            unsigned a0 = Qs[(wrow + lr    )*PQS + kb + qq];
            unsigned a1 = Qs[(wrow + lr + 8)*PQS + kb + qq];
            unsigned a2 = Qs[(wrow + lr    )*PQS + kb + qq + 4];
            unsigned a3 = Qs[(wrow + lr + 8)*PQS + kb + qq + 4];
            #pragma unroll
            for (int nt = 0; nt < 8; nt++) {
                unsigned b0 = Ks[(nt*8 + lr)*PKS + kb + qq];
                unsigned b1 = Ks[(nt*8 + lr)*PKS + kb + qq + 4];
                mma_tf32(S[nt], a0, a1, a2, a3, b0, b1);
            }
        }

        // ---- online softmax ----
        const float inv = 0.125f;   // 1/sqrt(64)
        float tm[2] = {-INFINITY, -INFINITY};
        #pragma unroll
        for (int nt = 0; nt < 8; nt++) {
            float b0 = bs[nt*8 + 2*qq];
            float b1 = bs[nt*8 + 2*qq + 1];
            S[nt][0] = S[nt][0]*inv + b0;  S[nt][1] = S[nt][1]*inv + b1;
            S[nt][2] = S[nt][2]*inv + b0;  S[nt][3] = S[nt][3]*inv + b1;
            tm[0] = fmaxf(tm[0], fmaxf(S[nt][0], S[nt][1]));
            tm[1] = fmaxf(tm[1], fmaxf(S[nt][2], S[nt][3]));
        }
        #pragma unroll
        for (int r = 0; r < 2; r++) {
            tm[r] = fmaxf(tm[r], __shfl_xor_sync(0xffffffffu, tm[r], 1));
            tm[r] = fmaxf(tm[r], __shfl_xor_sync(0xffffffffu, tm[r], 2));
        }
        float alpha[2], tl[2];
        #pragma unroll
        for (int r = 0; r < 2; r++) {
            float mn = fmaxf(mrow[r], tm[r]);
            alpha[r] = __expf(mrow[r] - mn);
            mrow[r] = mn;
            tl[r] = 0.0f;
            #pragma unroll
            for (int nt = 0; nt < 8; nt++) {
                float p0 = __expf(S[nt][2*r + 0] - mn);
                float p1 = __expf(S[nt][2*r + 1] - mn);
                S[nt][2*r + 0] = p0;  S[nt][2*r + 1] = p1;
                tl[r] += p0 + p1;
            }
            tl[r] += __shfl_xor_sync(0xffffffffu, tl[r], 1);
            tl[r] += __shfl_xor_sync(0xffffffffu, tl[r], 2);
            lrow[r] = lrow[r]*alpha[r] + tl[r];
            #pragma unroll
            for (int nt = 0; nt < 8; nt++) {
                O[nt][2*r + 0] *= alpha[r];
                O[nt][2*r + 1] *= alpha[r];
            }
        }

        // ---- write P (per-warp private region; only warp-level ordering needed) ----
        #pragma unroll
        for (int nt = 0; nt < 8; nt++) {
            Ps[(wrow + lr    )*PQS + nt*8 + 2*qq    ] = f2tf(S[nt][0]);
            Ps[(wrow + lr    )*PQS + nt*8 + 2*qq + 1] = f2tf(S[nt][1]);
            Ps[(wrow + lr + 8)*PQS + nt*8 + 2*qq    ] = f2tf(S[nt][2]);
            Ps[(wrow + lr + 8)*PQS + nt*8 + 2*qq + 1] = f2tf(S[nt][3]);
        }
        __syncwarp();

        // ---- O += P V ----
        #pragma unroll
        for (int ks = 0; ks < 8; ks++) {
            const int kb = ks * 8;
            unsigned a0 = Ps[(wrow + lr    )*PQS + kb + qq];
            unsigned a1 = Ps[(wrow + lr + 8)*PQS + kb + qq];
            unsigned a2 = Ps[(wrow + lr    )*PQS + kb + qq + 4];
            unsigned a3 = Ps[(wrow + lr + 8)*PQS + kb + qq + 4];
            #pragma unroll
            for (int nt = 0; nt < 8; nt++) {
                unsigned b0 = Vs[(kb + qq    )*PVS + nt*8 + lr];
                unsigned b1 = Vs[(kb + qq + 4)*PVS + nt*8 + lr];
                mma_tf32(O[nt], a0, a1, a2, a3, b0, b1);
            }
        }
        __syncwarp();   // PV reads of Ps done before next-iteration overwrite
    }

    // ---- epilogue: out[b, q, h*DK + d] ----
    const int b = bh >> 4, h = bh & (NHEAD - 1);
    #pragma unroll
    for (int r = 0; r < 2; r++) {
        float invl = 1.0f / lrow[r];
        int qrow = q0 + wrow + lr + r*8;
        size_t base = ((size_t)b*SEQ + qrow)*DMODEL + h*DK;
        #pragma unroll
        for (int nt = 0; nt < 8; nt++) {
            float2 v;
            v.x = O[nt][2*r + 0] * invl;
            v.y = O[nt][2*r + 1] * invl;
            *(float2*)&out[base + nt*8 + 2*qq] = v;
        }
    }
}

// ---------------- launch -----------------------------------------------------
extern "C" void kernel_launch(void* const* d_in, const int* in_sizes, int n_in,
                              void* d_out, int out_size)
{
    const float* input = (const float*)d_in[0];
    const void*  mask  = d_in[1];
    const float* Wq    = (const float*)d_in[2];
    const float* bq    = (const float*)d_in[3];
    const float* Wk    = (const float*)d_in[4];
    const float* bk    = (const float*)d_in[5];
    const float* Wv    = (const float*)d_in[6];
    const float* bv    = (const float*)d_in[7];
    float* out = (float*)d_out;

    float *qp, *kp, *vp;
    cudaGetSymbolAddress((void**)&qp, g_Q);
    cudaGetSymbolAddress((void**)&kp, g_K);
    cudaGetSymbolAddress((void**)&vp, g_V);

    detect_mask_kernel<<<1, 256>>>((const unsigned int*)mask);
    build_bias_kernel<<<(BATCH*SEQ + 255)/256, 256>>>(mask);

    dim3 ggrid(DMODEL/128, (BATCH*SEQ)/128);   // (8, 32)
    qkv_gemm_tc<<<ggrid, 256>>>(input, Wq, bq, qp);
    qkv_gemm_tc<<<ggrid, 256>>>(input, Wk, bk, kp);
    qkv_gemm_tc<<<ggrid, 256>>>(input, Wv, bv, vp);

    static int attn_smem_set = 0;
    const int smem_bytes = (QT*PQS + 64*PKS + 64*PVS + QT*PQS + 64) * sizeof(unsigned);
    if (!attn_smem_set) {
        cudaFuncSetAttribute(attn_tc_kernel,
                             cudaFuncAttributeMaxDynamicSharedMemorySize,
                             smem_bytes);
        attn_smem_set = 1;
    }
    dim3 agrid(SEQ/QT, BHTOT);                 // (16, 32)
    attn_tc_kernel<<<agrid, 256, smem_bytes>>>(out);
}